// round 5
// baseline (speedup 1.0000x reference)
#include <cuda_runtime.h>
#include <cuda_bf16.h>
#include <cstdint>

// Problem constants
#define Bsz   64
#define Tlen  256
#define INSZ  256
#define Hdim  64
#define Gdim  256        // 4*Hdim
#define Vocab 8000
#define Mrows (Bsz * Tlen)   // 16384

// Scratch (device globals; no allocation allowed in kernel_launch)
__device__ float g_xproj[Mrows * Gdim];
__device__ float g_h1[Mrows * Hdim];
// int8 split storage: row = 128 bytes: [0:64) = hi bytes, [64:128) = lo bytes
__device__ __align__(128) signed char g_A8[Mrows * 128];
__device__ __align__(128) signed char g_B8[Vocab * 128];

// ---------------- packed f32x2 helpers ----------------
__device__ __forceinline__ unsigned long long pack2(float x) {
    unsigned long long r;
    asm("mov.b64 %0, {%1, %1};" : "=l"(r) : "f"(x));
    return r;
}
__device__ __forceinline__ unsigned long long pack2v(float x, float y) {
    unsigned long long r;
    asm("mov.b64 %0, {%1, %2};" : "=l"(r) : "f"(x), "f"(y));
    return r;
}
__device__ __forceinline__ void fma2(unsigned long long& d, unsigned long long a,
                                     unsigned long long b) {
    asm("fma.rn.f32x2 %0, %1, %2, %0;" : "+l"(d) : "l"(a), "l"(b));
}
__device__ __forceinline__ float2 unpack2(unsigned long long v) {
    float2 f;
    asm("mov.b64 {%0, %1}, %2;" : "=f"(f.x), "=f"(f.y) : "l"(v));
    return f;
}
__device__ __forceinline__ float fast_rcp(float x) {
    float r;
    asm("rcp.approx.f32 %0, %1;" : "=f"(r) : "f"(x));
    return r;
}
__device__ __forceinline__ float sigmoidf_(float x) {
    return fast_rcp(1.0f + __expf(-x));
}
__device__ __forceinline__ float tanh_fast(float x) {
    return 1.0f - 2.0f * fast_rcp(1.0f + __expf(2.0f * x));
}

// ---------------- generic C[M,N] = A[M,K] * B[N,K]^T + bias1 (+bias2) ----------------
__global__ void gemm_nt_bias(const float* __restrict__ A, const float* __restrict__ Bm,
                             const float* __restrict__ bias1, const float* __restrict__ bias2,
                             float* __restrict__ C, int M, int N, int K)
{
    __shared__ __align__(16) float As[64][17];
    __shared__ __align__(16) float Bs[16][68];

    const int t  = threadIdx.x;
    const int bm = blockIdx.y * 64;
    const int bn = blockIdx.x * 64;
    const int tm = (t >> 4) << 2;
    const int tn = (t & 15) << 2;
    const int lr = t >> 2;
    const int lk = (t & 3) << 2;

    unsigned long long acc[4][2];
#pragma unroll
    for (int i = 0; i < 4; i++) { acc[i][0] = 0ULL; acc[i][1] = 0ULL; }

    const float* Aptr = A  + (size_t)(bm + lr) * K + lk;
    const float* Bptr = Bm + (size_t)(bn + lr) * K + lk;

    for (int k0 = 0; k0 < K; k0 += 16) {
        float4 av = *reinterpret_cast<const float4*>(Aptr + k0);
        float4 bv = *reinterpret_cast<const float4*>(Bptr + k0);
        As[lr][lk + 0] = av.x; As[lr][lk + 1] = av.y;
        As[lr][lk + 2] = av.z; As[lr][lk + 3] = av.w;
        Bs[lk + 0][lr] = bv.x; Bs[lk + 1][lr] = bv.y;
        Bs[lk + 2][lr] = bv.z; Bs[lk + 3][lr] = bv.w;
        __syncthreads();
#pragma unroll
        for (int kk = 0; kk < 16; kk++) {
            unsigned long long b0 =
                *reinterpret_cast<const unsigned long long*>(&Bs[kk][tn]);
            unsigned long long b1 =
                *reinterpret_cast<const unsigned long long*>(&Bs[kk][tn + 2]);
#pragma unroll
            for (int i = 0; i < 4; i++) {
                unsigned long long ap = pack2(As[tm + i][kk]);
                fma2(acc[i][0], ap, b0);
                fma2(acc[i][1], ap, b1);
            }
        }
        __syncthreads();
    }

    float4 bvec;
    bvec.x = bias1[bn + tn + 0];
    bvec.y = bias1[bn + tn + 1];
    bvec.z = bias1[bn + tn + 2];
    bvec.w = bias1[bn + tn + 3];
    if (bias2) {
        bvec.x += bias2[bn + tn + 0];
        bvec.y += bias2[bn + tn + 1];
        bvec.z += bias2[bn + tn + 2];
        bvec.w += bias2[bn + tn + 3];
    }
#pragma unroll
    for (int i = 0; i < 4; i++) {
        float2 lo = unpack2(acc[i][0]);
        float2 hi = unpack2(acc[i][1]);
        float4 v = make_float4(lo.x + bvec.x, lo.y + bvec.y,
                               hi.x + bvec.z, hi.y + bvec.w);
        *reinterpret_cast<float4*>(&C[(size_t)(bm + tm + i) * N + bn + tn]) = v;
    }
}

// ---------------- LSTM recurrence (identical math to R3/R4 passing version) ---------
// If a8_out != null, h is stored as an exact int8 split: a16 = rint(h*2^14),
// a16 = 256*ahi + alo, row layout [hi bytes 0..63 | lo bytes 64..127].
__global__ void lstm_layer(const float* __restrict__ xproj,
                           const float* __restrict__ Whh,
                           float* __restrict__ hout,
                           signed char* __restrict__ a8_out)
{
    __shared__ __align__(16) float h_sh[Hdim];
    __shared__ float gate_sh[Gdim];

    const int b = blockIdx.x;
    const int g = threadIdx.x;
    const int blk = g >> 6;

    unsigned long long wp[Hdim / 2];
#pragma unroll
    for (int j = 0; j < Hdim / 2; j++) {
        float2 v = *reinterpret_cast<const float2*>(Whh + g * Hdim + 2 * j);
        wp[j] = pack2v(v.x, v.y);
    }

    float c = 0.0f;
    if (g < Hdim) h_sh[g] = 0.0f;
    __syncthreads();

    const float* xp = xproj + (size_t)b * Tlen * Gdim;
    float xcur = xp[g];

    const unsigned long long* hp =
        reinterpret_cast<const unsigned long long*>(h_sh);

    for (int t = 0; t < Tlen; t++) {
        unsigned long long a0 = 0ULL, a1 = 0ULL, a2 = 0ULL, a3 = 0ULL;
        float xnext = (t + 1 < Tlen) ? xp[(size_t)(t + 1) * Gdim + g] : 0.0f;
#pragma unroll
        for (int j = 0; j < Hdim / 2; j += 4) {
            fma2(a0, wp[j + 0], hp[j + 0]);
            fma2(a1, wp[j + 1], hp[j + 1]);
            fma2(a2, wp[j + 2], hp[j + 2]);
            fma2(a3, wp[j + 3], hp[j + 3]);
        }
        float2 s0 = unpack2(a0), s1 = unpack2(a1), s2 = unpack2(a2), s3 = unpack2(a3);
        float val = xcur + (((s0.x + s0.y) + (s1.x + s1.y)) +
                            ((s2.x + s2.y) + (s3.x + s3.y)));
        xcur = xnext;

        float act = (blk == 2) ? tanh_fast(val) : sigmoidf_(val);
        gate_sh[g] = act;
        __syncthreads();

        if (g < Hdim) {
            float iv = gate_sh[g];
            float fv = gate_sh[g + Hdim];
            float gv = gate_sh[g + 2 * Hdim];
            float ov = gate_sh[g + 3 * Hdim];
            c = fv * c + iv * gv;
            float hn = ov * tanh_fast(c);
            h_sh[g] = hn;
            if (hout) hout[((size_t)b * Tlen + t) * Hdim + g] = hn;
            if (a8_out) {
                int a16 = __float2int_rn(hn * 16384.0f);
                int alo = ((a16 + 128) & 255) - 128;
                int ahi = (a16 - alo) >> 8;
                size_t rowoff = ((size_t)b * Tlen + t) * 128;
                a8_out[rowoff + g] = (signed char)ahi;
                a8_out[rowoff + 64 + g] = (signed char)alo;
            }
        }
        __syncthreads();
    }
}

// ---------------- Wl -> int8 split conversion ------------------
__global__ void cvt_b8(const float* __restrict__ in, signed char* __restrict__ out, int n)
{
    int i = blockIdx.x * blockDim.x + threadIdx.x;
    if (i < n) {
        int v = i >> 6;
        int h = i & 63;
        int b16 = __float2int_rn(in[i] * 131072.0f);   // |Wl| <= 0.125 -> |b16| <= 16384
        int blo = ((b16 + 128) & 255) - 128;
        int bhi = (b16 - blo) >> 8;
        out[(size_t)v * 128 + h] = (signed char)bhi;
        out[(size_t)v * 128 + 64 + h] = (signed char)blo;
    }
}

// ============ IMMA int8 logits GEMM, streaming/pipelined ============================
// C = (2^16*P1 + 2^8*P2) / 2^31 + bias,  P1 = Ahi*Bhi, P2 = Ahi*Blo + Alo*Bhi.
// CTA: one bn (64 vocab cols, B resident 8KB) x 8 m-tiles of 128 rows, A double-buffered.
#define SWZ128(off) ((off) ^ (((off) >> 3) & 0x70))
#define LS_B    0
#define LS_A    8192
#define LS_ASTG 16384          // per A stage: 128 rows x 128B (hi|lo packed)
#define LG_SMEM (8192 + 2 * 16384 + 1024)
#define NM_TILES 8

static __device__ __forceinline__ uint32_t smem_u32(const void* p) {
    uint32_t a;
    asm("{ .reg .u64 t; cvta.to.shared.u64 t, %1; cvt.u32.u64 %0, t; }"
        : "=r"(a) : "l"(p));
    return a;
}
__device__ __forceinline__ void cp16(uint32_t dst, const void* src) {
    asm volatile("cp.async.cg.shared.global [%0], [%1], 16;"
                 :: "r"(dst), "l"(src));
}
__device__ __forceinline__ void cp_commit() {
    asm volatile("cp.async.commit_group;" ::: "memory");
}
template <int N>
__device__ __forceinline__ void cp_wait() {
    asm volatile("cp.async.wait_group %0;" :: "n"(N) : "memory");
}
__device__ __forceinline__ void ldsm_x4(uint32_t& r0, uint32_t& r1, uint32_t& r2,
                                        uint32_t& r3, uint32_t addr) {
    asm volatile("ldmatrix.sync.aligned.m8n8.x4.shared.b16 {%0,%1,%2,%3}, [%4];"
                 : "=r"(r0), "=r"(r1), "=r"(r2), "=r"(r3) : "r"(addr));
}
__device__ __forceinline__ void mma_s8(int* c, uint32_t a0, uint32_t a1,
                                       uint32_t a2, uint32_t a3,
                                       uint32_t b0, uint32_t b1) {
    asm volatile("mma.sync.aligned.m16n8k32.row.col.s32.s8.s8.s32 "
                 "{%0,%1,%2,%3}, {%4,%5,%6,%7}, {%8,%9}, {%0,%1,%2,%3};"
                 : "+r"(c[0]), "+r"(c[1]), "+r"(c[2]), "+r"(c[3])
                 : "r"(a0), "r"(a1), "r"(a2), "r"(a3), "r"(b0), "r"(b1));
}
__device__ __forceinline__ void stg_cs_f2(float* p, float x, float y) {
    asm volatile("st.global.cs.v2.f32 [%0], {%1,%2};" :: "l"(p), "f"(x), "f"(y));
}

__device__ __forceinline__ void load_A_stage(uint32_t sA, const signed char* A8,
                                             int bm, int tid) {
    const int row = tid >> 1;            // 0..127
    const int cb = (tid & 1) * 4;        // chunk base 0 or 4
    const signed char* src = A8 + (size_t)(bm + row) * 128;
#pragma unroll
    for (int i = 0; i < 4; i++) {
        uint32_t off = SWZ128((uint32_t)(row * 128 + (cb + i) * 16));
        cp16(sA + off, src + (cb + i) * 16);
    }
}

__global__ void __launch_bounds__(256)
logits_gemm(const signed char* __restrict__ A8, const signed char* __restrict__ B8,
            const float* __restrict__ bias, float* __restrict__ C)
{
    extern __shared__ char smem_raw[];
    const uint32_t sb0 = smem_u32(smem_raw);
    const uint32_t sb = (sb0 + 1023) & ~1023u;

    const int tid = threadIdx.x;
    const int lane = tid & 31;
    const int wid = tid >> 5;
    const int wm = wid & 3;        // warp m-tile (0..3)
    const int wn = wid >> 2;       // warp n-tile (0..1)
    const int bn = blockIdx.x * 64;
    const int bm0 = blockIdx.y * (NM_TILES * 128);

    // ---- resident B tile (64 rows x 128B hi|lo), cp.async ----
    {
        const int row = tid >> 2;            // 0..63
        const int cb = (tid & 3) * 2;        // chunks 0,2,4,6
        const signed char* src = B8 + (size_t)(bn + row) * 128;
#pragma unroll
        for (int i = 0; i < 2; i++) {
            uint32_t off = SWZ128((uint32_t)(row * 128 + (cb + i) * 16));
            cp16(sb + LS_B + off, src + (cb + i) * 16);
        }
    }
    load_A_stage(sb + LS_A, A8, bm0, tid);
    cp_commit();

    const int gid = lane >> 2;
    const int tig = lane & 3;
    float2 bv[4];
#pragma unroll
    for (int nt = 0; nt < 4; nt++)
        bv[nt] = *reinterpret_cast<const float2*>(bias + bn + wn * 32 + nt * 8 + 2 * tig);

    const int rsel = lane & 15;
    const int csel = lane >> 4;

    for (int it = 0; it < NM_TILES; it++) {
        const uint32_t sA = sb + LS_A + (it & 1) * LS_ASTG;
        if (it + 1 < NM_TILES) {
            load_A_stage(sb + LS_A + ((it + 1) & 1) * LS_ASTG, A8,
                         bm0 + (it + 1) * 128, tid);
            cp_commit();
            cp_wait<1>();
        } else {
            cp_wait<0>();
        }
        __syncthreads();

        int accP1[2][4][4], accP2[2][4][4];
#pragma unroll
        for (int i = 0; i < 2; i++)
#pragma unroll
            for (int j = 0; j < 4; j++)
#pragma unroll
                for (int q = 0; q < 4; q++) { accP1[i][j][q] = 0; accP2[i][j][q] = 0; }

        // pass p: 0 = hi*hi -> P1, 1 = hi*lo -> P2, 2 = lo*hi -> P2
#pragma unroll
        for (int p = 0; p < 3; p++) {
            const int aC = (p == 2) ? 4 : 0;   // A chunk base (hi=0, lo=4)
            const int bC = (p == 1) ? 4 : 0;   // B chunk base
#pragma unroll
            for (int ks = 0; ks < 2; ks++) {
                uint32_t a[2][4];
#pragma unroll
                for (int mt = 0; mt < 2; mt++) {
                    int row = wm * 32 + mt * 16 + rsel;
                    uint32_t addr = sA + SWZ128((uint32_t)(row * 128 + (aC + ks * 2 + csel) * 16));
                    ldsm_x4(a[mt][0], a[mt][1], a[mt][2], a[mt][3], addr);
                }
                uint32_t b0[4], b1[4];
#pragma unroll
                for (int np = 0; np < 2; np++) {
                    int row = wn * 32 + np * 16 + rsel;
                    uint32_t addr = sb + LS_B + SWZ128((uint32_t)(row * 128 + (bC + ks * 2 + csel) * 16));
                    uint32_t r0, r1, r2, r3;
                    ldsm_x4(r0, r1, r2, r3, addr);
                    b0[np * 2 + 0] = r0; b0[np * 2 + 1] = r1;
                    b1[np * 2 + 0] = r2; b1[np * 2 + 1] = r3;
                }
                int (*acc)[4][4] = (p == 0) ? accP1 : accP2;
#pragma unroll
                for (int mt = 0; mt < 2; mt++)
#pragma unroll
                    for (int nt = 0; nt < 4; nt++)
                        mma_s8(acc[mt][nt], a[mt][0], a[mt][1], a[mt][2], a[mt][3],
                               b0[nt], b1[nt]);
            }
        }

        // epilogue: v = P1*2^-15 + P2*2^-23 + bias  (exact int -> fp32 conversions)
        const float S1 = 3.0517578125e-05f;        // 2^-15
        const float S2 = 1.1920928955078125e-07f;  // 2^-23
        const int bm = bm0 + it * 128;
#pragma unroll
        for (int nt = 0; nt < 4; nt++) {
            const int gn = bn + wn * 32 + nt * 8 + 2 * tig;
#pragma unroll
            for (int mt = 0; mt < 2; mt++) {
                const int gm0 = bm + wm * 32 + mt * 16 + gid;
                float x0 = fmaf((float)accP1[mt][nt][0], S1,
                                fmaf((float)accP2[mt][nt][0], S2, bv[nt].x));
                float y0 = fmaf((float)accP1[mt][nt][1], S1,
                                fmaf((float)accP2[mt][nt][1], S2, bv[nt].y));
                float x1 = fmaf((float)accP1[mt][nt][2], S1,
                                fmaf((float)accP2[mt][nt][2], S2, bv[nt].x));
                float y1 = fmaf((float)accP1[mt][nt][3], S1,
                                fmaf((float)accP2[mt][nt][3], S2, bv[nt].y));
                stg_cs_f2(C + (size_t)gm0 * Vocab + gn, x0, y0);
                stg_cs_f2(C + (size_t)(gm0 + 8) * Vocab + gn, x1, y1);
            }
        }
        __syncthreads();
    }
}

// ------------------------------------ launch --------------------------------------
extern "C" void kernel_launch(void* const* d_in, const int* in_sizes, int n_in,
                              void* d_out, int out_size)
{
    (void)in_sizes; (void)n_in; (void)out_size;
    const float* x     = (const float*)d_in[0];
    const float* W_ih0 = (const float*)d_in[1];
    const float* W_hh0 = (const float*)d_in[2];
    const float* b_ih0 = (const float*)d_in[3];
    const float* b_hh0 = (const float*)d_in[4];
    const float* W_ih1 = (const float*)d_in[5];
    const float* W_hh1 = (const float*)d_in[6];
    const float* b_ih1 = (const float*)d_in[7];
    const float* b_hh1 = (const float*)d_in[8];
    const float* Wl    = (const float*)d_in[9];
    const float* bl    = (const float*)d_in[10];
    float* out = (float*)d_out;

    void* p;
    cudaGetSymbolAddress(&p, g_xproj); float* xproj = (float*)p;
    cudaGetSymbolAddress(&p, g_h1);    float* h1    = (float*)p;
    cudaGetSymbolAddress(&p, g_A8);    signed char* A8 = (signed char*)p;
    cudaGetSymbolAddress(&p, g_B8);    signed char* B8 = (signed char*)p;

    // Wl int8 split (independent of LSTM chain)
    cvt_b8<<<(Vocab * Hdim + 255) / 256, 256>>>(Wl, B8, Vocab * Hdim);

    // Layer 0 input projection
    gemm_nt_bias<<<dim3(Gdim / 64, Mrows / 64), 256>>>(
        x, W_ih0, b_ih0, b_hh0, xproj, Mrows, Gdim, INSZ);
    // Layer 0 recurrence -> h1 (fp32)
    lstm_layer<<<Bsz, Gdim>>>(xproj, W_hh0, h1, nullptr);
    // Layer 1 input projection
    gemm_nt_bias<<<dim3(Gdim / 64, Mrows / 64), 256>>>(
        h1, W_ih1, b_ih1, b_hh1, xproj, Mrows, Gdim, Hdim);
    // Layer 1 recurrence -> int8 split directly
    lstm_layer<<<Bsz, Gdim>>>(xproj, W_hh1, nullptr, A8);

    // Logits via pipelined IMMA int8 3-pass split
    cudaFuncSetAttribute(logits_gemm, cudaFuncAttributeMaxDynamicSharedMemorySize, LG_SMEM);
    logits_gemm<<<dim3(Vocab / 64, Mrows / (NM_TILES * 128)), 256, LG_SMEM>>>(
        A8, B8, bl, out);
}

// round 6
// speedup vs baseline: 1.4553x; 1.4553x over previous
#include <cuda_runtime.h>
#include <cuda_fp16.h>
#include <cstdint>

// Problem constants
#define Bsz   64
#define Tlen  256
#define INSZ  256
#define Hdim  64
#define Gdim  256        // 4*Hdim
#define Vocab 8000
#define Mrows (Bsz * Tlen)   // 16384

// Scratch (device globals; no allocation allowed in kernel_launch)
__device__ float g_xproj[Mrows * Gdim];
__device__ float g_h1[Mrows * Hdim];
__device__ __align__(128) __half g_Ah[Mrows * Hdim];    // A rounded to fp16
__device__ __align__(128) __half g_Bhi[Vocab * Hdim];   // 8*Wl hi
__device__ __align__(128) __half g_Blo[Vocab * Hdim];   // 8*Wl lo

// ---------------- packed f32x2 helpers ----------------
__device__ __forceinline__ unsigned long long pack2(float x) {
    unsigned long long r;
    asm("mov.b64 %0, {%1, %1};" : "=l"(r) : "f"(x));
    return r;
}
__device__ __forceinline__ unsigned long long pack2v(float x, float y) {
    unsigned long long r;
    asm("mov.b64 %0, {%1, %2};" : "=l"(r) : "f"(x), "f"(y));
    return r;
}
__device__ __forceinline__ void fma2(unsigned long long& d, unsigned long long a,
                                     unsigned long long b) {
    asm("fma.rn.f32x2 %0, %1, %2, %0;" : "+l"(d) : "l"(a), "l"(b));
}
__device__ __forceinline__ float2 unpack2(unsigned long long v) {
    float2 f;
    asm("mov.b64 {%0, %1}, %2;" : "=f"(f.x), "=f"(f.y) : "l"(v));
    return f;
}
__device__ __forceinline__ float fast_rcp(float x) {
    float r;
    asm("rcp.approx.f32 %0, %1;" : "=f"(r) : "f"(x));
    return r;
}
__device__ __forceinline__ float sigmoidf_(float x) {
    return fast_rcp(1.0f + __expf(-x));
}
__device__ __forceinline__ float tanh_fast(float x) {
    return 1.0f - 2.0f * fast_rcp(1.0f + __expf(2.0f * x));
}

// ---------------- generic C[M,N] = A[M,K] * B[N,K]^T + bias1 (+bias2) ----------------
__global__ void gemm_nt_bias(const float* __restrict__ A, const float* __restrict__ Bm,
                             const float* __restrict__ bias1, const float* __restrict__ bias2,
                             float* __restrict__ C, int M, int N, int K)
{
    __shared__ __align__(16) float As[64][17];
    __shared__ __align__(16) float Bs[16][68];

    const int t  = threadIdx.x;
    const int bm = blockIdx.y * 64;
    const int bn = blockIdx.x * 64;
    const int tm = (t >> 4) << 2;
    const int tn = (t & 15) << 2;
    const int lr = t >> 2;
    const int lk = (t & 3) << 2;

    unsigned long long acc[4][2];
#pragma unroll
    for (int i = 0; i < 4; i++) { acc[i][0] = 0ULL; acc[i][1] = 0ULL; }

    const float* Aptr = A  + (size_t)(bm + lr) * K + lk;
    const float* Bptr = Bm + (size_t)(bn + lr) * K + lk;

    for (int k0 = 0; k0 < K; k0 += 16) {
        float4 av = *reinterpret_cast<const float4*>(Aptr + k0);
        float4 bv = *reinterpret_cast<const float4*>(Bptr + k0);
        As[lr][lk + 0] = av.x; As[lr][lk + 1] = av.y;
        As[lr][lk + 2] = av.z; As[lr][lk + 3] = av.w;
        Bs[lk + 0][lr] = bv.x; Bs[lk + 1][lr] = bv.y;
        Bs[lk + 2][lr] = bv.z; Bs[lk + 3][lr] = bv.w;
        __syncthreads();
#pragma unroll
        for (int kk = 0; kk < 16; kk++) {
            unsigned long long b0 =
                *reinterpret_cast<const unsigned long long*>(&Bs[kk][tn]);
            unsigned long long b1 =
                *reinterpret_cast<const unsigned long long*>(&Bs[kk][tn + 2]);
#pragma unroll
            for (int i = 0; i < 4; i++) {
                unsigned long long ap = pack2(As[tm + i][kk]);
                fma2(acc[i][0], ap, b0);
                fma2(acc[i][1], ap, b1);
            }
        }
        __syncthreads();
    }

    float4 bvec;
    bvec.x = bias1[bn + tn + 0];
    bvec.y = bias1[bn + tn + 1];
    bvec.z = bias1[bn + tn + 2];
    bvec.w = bias1[bn + tn + 3];
    if (bias2) {
        bvec.x += bias2[bn + tn + 0];
        bvec.y += bias2[bn + tn + 1];
        bvec.z += bias2[bn + tn + 2];
        bvec.w += bias2[bn + tn + 3];
    }
#pragma unroll
    for (int i = 0; i < 4; i++) {
        float2 lo = unpack2(acc[i][0]);
        float2 hi = unpack2(acc[i][1]);
        float4 v = make_float4(lo.x + bvec.x, lo.y + bvec.y,
                               hi.x + bvec.z, hi.y + bvec.w);
        *reinterpret_cast<float4*>(&C[(size_t)(bm + tm + i) * N + bn + tn]) = v;
    }
}

// ---------------- LSTM recurrence (identical math to R3/R4 passing version) ---------
__global__ void lstm_layer(const float* __restrict__ xproj,
                           const float* __restrict__ Whh,
                           float* __restrict__ hout,
                           __half* __restrict__ ah_out)
{
    __shared__ __align__(16) float h_sh[Hdim];
    __shared__ float gate_sh[Gdim];

    const int b = blockIdx.x;
    const int g = threadIdx.x;
    const int blk = g >> 6;

    unsigned long long wp[Hdim / 2];
#pragma unroll
    for (int j = 0; j < Hdim / 2; j++) {
        float2 v = *reinterpret_cast<const float2*>(Whh + g * Hdim + 2 * j);
        wp[j] = pack2v(v.x, v.y);
    }

    float c = 0.0f;
    if (g < Hdim) h_sh[g] = 0.0f;
    __syncthreads();

    const float* xp = xproj + (size_t)b * Tlen * Gdim;
    float xcur = xp[g];

    const unsigned long long* hp =
        reinterpret_cast<const unsigned long long*>(h_sh);

    for (int t = 0; t < Tlen; t++) {
        unsigned long long a0 = 0ULL, a1 = 0ULL, a2 = 0ULL, a3 = 0ULL;
        float xnext = (t + 1 < Tlen) ? xp[(size_t)(t + 1) * Gdim + g] : 0.0f;
#pragma unroll
        for (int j = 0; j < Hdim / 2; j += 4) {
            fma2(a0, wp[j + 0], hp[j + 0]);
            fma2(a1, wp[j + 1], hp[j + 1]);
            fma2(a2, wp[j + 2], hp[j + 2]);
            fma2(a3, wp[j + 3], hp[j + 3]);
        }
        float2 s0 = unpack2(a0), s1 = unpack2(a1), s2 = unpack2(a2), s3 = unpack2(a3);
        float val = xcur + (((s0.x + s0.y) + (s1.x + s1.y)) +
                            ((s2.x + s2.y) + (s3.x + s3.y)));
        xcur = xnext;

        float act = (blk == 2) ? tanh_fast(val) : sigmoidf_(val);
        gate_sh[g] = act;
        __syncthreads();

        if (g < Hdim) {
            float iv = gate_sh[g];
            float fv = gate_sh[g + Hdim];
            float gv = gate_sh[g + 2 * Hdim];
            float ov = gate_sh[g + 3 * Hdim];
            c = fv * c + iv * gv;
            float hn = ov * tanh_fast(c);
            h_sh[g] = hn;
            size_t idx = ((size_t)b * Tlen + t) * Hdim + g;
            if (hout) hout[idx] = hn;
            if (ah_out) ah_out[idx] = __float2half(hn);
        }
        __syncthreads();
    }
}

// ---------------- Wl -> fp16 2-term split (scaled by 8 for fp16 normal range) -------
__global__ void cvt_bh(const float* __restrict__ in, __half* __restrict__ hi,
                       __half* __restrict__ lo, int n)
{
    int i = blockIdx.x * blockDim.x + threadIdx.x;
    if (i < n) {
        float v = in[i] * 8.0f;              // |Wl| <= 0.125 -> |v| <= 1
        __half h = __float2half(v);
        hi[i] = h;
        lo[i] = __float2half(v - __half2float(h));
    }
}

// ============ HMMA fp16 logits GEMM, streaming/pipelined, 2-pass ====================
// C = A_f16 * (Bhi + Blo)^T / 8 + bias.
// CTA: one bn (64 vocab cols, B hi/lo resident 16KB) x 8 m-tiles of 128 rows,
// A single-fp16 double-buffered (2 x 16KB) via cp.async.
#define SWZ128(off) ((off) ^ (((off) >> 3) & 0x70))
#define LS_BHI  0
#define LS_BLO  8192
#define LS_A    16384
#define LS_ASTG 16384
#define LG_SMEM (16384 + 2 * 16384 + 1024)
#define NM_TILES 8

static __device__ __forceinline__ uint32_t smem_u32(const void* p) {
    uint32_t a;
    asm("{ .reg .u64 t; cvta.to.shared.u64 t, %1; cvt.u32.u64 %0, t; }"
        : "=r"(a) : "l"(p));
    return a;
}
__device__ __forceinline__ void cp16(uint32_t dst, const void* src) {
    asm volatile("cp.async.cg.shared.global [%0], [%1], 16;"
                 :: "r"(dst), "l"(src));
}
__device__ __forceinline__ void cp_commit() {
    asm volatile("cp.async.commit_group;" ::: "memory");
}
template <int N>
__device__ __forceinline__ void cp_wait() {
    asm volatile("cp.async.wait_group %0;" :: "n"(N) : "memory");
}
__device__ __forceinline__ void ldsm_x4(uint32_t& r0, uint32_t& r1, uint32_t& r2,
                                        uint32_t& r3, uint32_t addr) {
    asm volatile("ldmatrix.sync.aligned.m8n8.x4.shared.b16 {%0,%1,%2,%3}, [%4];"
                 : "=r"(r0), "=r"(r1), "=r"(r2), "=r"(r3) : "r"(addr));
}
__device__ __forceinline__ void mma_f16(float* c, uint32_t a0, uint32_t a1,
                                        uint32_t a2, uint32_t a3,
                                        uint32_t b0, uint32_t b1) {
    asm volatile("mma.sync.aligned.m16n8k16.row.col.f32.f16.f16.f32 "
                 "{%0,%1,%2,%3}, {%4,%5,%6,%7}, {%8,%9}, {%0,%1,%2,%3};"
                 : "+f"(c[0]), "+f"(c[1]), "+f"(c[2]), "+f"(c[3])
                 : "r"(a0), "r"(a1), "r"(a2), "r"(a3), "r"(b0), "r"(b1));
}
__device__ __forceinline__ void stg_cs_f2(float* p, float x, float y) {
    asm volatile("st.global.cs.v2.f32 [%0], {%1,%2};" :: "l"(p), "f"(x), "f"(y));
}

__device__ __forceinline__ void load_A_stage(uint32_t sA, const __half* Ah,
                                             int bm, int tid) {
    const int row = tid >> 1;            // 0..127
    const int cb = (tid & 1) * 4;        // chunk base 0 or 4
    const char* src = reinterpret_cast<const char*>(Ah + (size_t)(bm + row) * Hdim);
#pragma unroll
    for (int i = 0; i < 4; i++) {
        uint32_t off = SWZ128((uint32_t)(row * 128 + (cb + i) * 16));
        cp16(sA + off, src + (cb + i) * 16);
    }
}

__global__ void __launch_bounds__(256)
logits_gemm(const __half* __restrict__ Ah, const __half* __restrict__ Bhi,
            const __half* __restrict__ Blo, const float* __restrict__ bias,
            float* __restrict__ C)
{
    extern __shared__ char smem_raw[];
    const uint32_t sb0 = smem_u32(smem_raw);
    const uint32_t sb = (sb0 + 1023) & ~1023u;

    const int tid = threadIdx.x;
    const int lane = tid & 31;
    const int wid = tid >> 5;
    const int wm = wid & 3;        // warp m-tile (0..3)
    const int wn = wid >> 2;       // warp n-tile (0..1)
    const int bn = blockIdx.x * 64;
    const int bm0 = blockIdx.y * (NM_TILES * 128);

    // ---- resident B hi/lo tiles (64 rows x 128B each), cp.async ----
    {
        const int row = tid >> 2;            // 0..63
        const int cb = (tid & 3) * 2;        // chunks 0,2,4,6
        const char* sh = reinterpret_cast<const char*>(Bhi + (size_t)(bn + row) * Hdim);
        const char* sl = reinterpret_cast<const char*>(Blo + (size_t)(bn + row) * Hdim);
#pragma unroll
        for (int i = 0; i < 2; i++) {
            uint32_t off = SWZ128((uint32_t)(row * 128 + (cb + i) * 16));
            cp16(sb + LS_BHI + off, sh + (cb + i) * 16);
            cp16(sb + LS_BLO + off, sl + (cb + i) * 16);
        }
    }
    load_A_stage(sb + LS_A, Ah, bm0, tid);
    cp_commit();

    const int gid = lane >> 2;
    const int tig = lane & 3;
    float2 bv[4];
#pragma unroll
    for (int nt = 0; nt < 4; nt++)
        bv[nt] = *reinterpret_cast<const float2*>(bias + bn + wn * 32 + nt * 8 + 2 * tig);

    const int rsel = lane & 15;
    const int csel = lane >> 4;

    for (int it = 0; it < NM_TILES; it++) {
        const uint32_t sA = sb + LS_A + (it & 1) * LS_ASTG;
        if (it + 1 < NM_TILES) {
            load_A_stage(sb + LS_A + ((it + 1) & 1) * LS_ASTG, Ah,
                         bm0 + (it + 1) * 128, tid);
            cp_commit();
            cp_wait<1>();
        } else {
            cp_wait<0>();
        }
        __syncthreads();

        float acc[2][4][4];
#pragma unroll
        for (int i = 0; i < 2; i++)
#pragma unroll
            for (int j = 0; j < 4; j++)
#pragma unroll
                for (int q = 0; q < 4; q++) acc[i][j][q] = 0.0f;

#pragma unroll
        for (int ks = 0; ks < 4; ks++) {
            const int col16 = ks * 2 + csel;
            // A fragments (shared by both passes)
            uint32_t a[2][4];
#pragma unroll
            for (int mt = 0; mt < 2; mt++) {
                int row = wm * 32 + mt * 16 + rsel;
                uint32_t addr = sA + SWZ128((uint32_t)(row * 128 + col16 * 16));
                ldsm_x4(a[mt][0], a[mt][1], a[mt][2], a[mt][3], addr);
            }
            // pass 0: Bhi, pass 1: Blo — both accumulate into acc
#pragma unroll
            for (int p = 0; p < 2; p++) {
                const uint32_t bB = sb + (p == 0 ? LS_BHI : LS_BLO);
                uint32_t b0[4], b1[4];
#pragma unroll
                for (int np = 0; np < 2; np++) {
                    int row = wn * 32 + np * 16 + rsel;
                    uint32_t addr = bB + SWZ128((uint32_t)(row * 128 + col16 * 16));
                    uint32_t r0, r1, r2, r3;
                    ldsm_x4(r0, r1, r2, r3, addr);
                    b0[np * 2 + 0] = r0; b0[np * 2 + 1] = r1;
                    b1[np * 2 + 0] = r2; b1[np * 2 + 1] = r3;
                }
#pragma unroll
                for (int mt = 0; mt < 2; mt++)
#pragma unroll
                    for (int nt = 0; nt < 4; nt++)
                        mma_f16(acc[mt][nt], a[mt][0], a[mt][1], a[mt][2], a[mt][3],
                                b0[nt], b1[nt]);
            }
        }

        // epilogue: C = acc/8 + bias, streaming stores
        const int bm = bm0 + it * 128;
#pragma unroll
        for (int nt = 0; nt < 4; nt++) {
            const int gn = bn + wn * 32 + nt * 8 + 2 * tig;
#pragma unroll
            for (int mt = 0; mt < 2; mt++) {
                const int gm0 = bm + wm * 32 + mt * 16 + gid;
                float x0 = fmaf(acc[mt][nt][0], 0.125f, bv[nt].x);
                float y0 = fmaf(acc[mt][nt][1], 0.125f, bv[nt].y);
                float x1 = fmaf(acc[mt][nt][2], 0.125f, bv[nt].x);
                float y1 = fmaf(acc[mt][nt][3], 0.125f, bv[nt].y);
                stg_cs_f2(C + (size_t)gm0 * Vocab + gn, x0, y0);
                stg_cs_f2(C + (size_t)(gm0 + 8) * Vocab + gn, x1, y1);
            }
        }
        __syncthreads();
    }
}

// ------------------------------------ launch --------------------------------------
extern "C" void kernel_launch(void* const* d_in, const int* in_sizes, int n_in,
                              void* d_out, int out_size)
{
    (void)in_sizes; (void)n_in; (void)out_size;
    const float* x     = (const float*)d_in[0];
    const float* W_ih0 = (const float*)d_in[1];
    const float* W_hh0 = (const float*)d_in[2];
    const float* b_ih0 = (const float*)d_in[3];
    const float* b_hh0 = (const float*)d_in[4];
    const float* W_ih1 = (const float*)d_in[5];
    const float* W_hh1 = (const float*)d_in[6];
    const float* b_ih1 = (const float*)d_in[7];
    const float* b_hh1 = (const float*)d_in[8];
    const float* Wl    = (const float*)d_in[9];
    const float* bl    = (const float*)d_in[10];
    float* out = (float*)d_out;

    void* p;
    cudaGetSymbolAddress(&p, g_xproj); float* xproj = (float*)p;
    cudaGetSymbolAddress(&p, g_h1);    float* h1    = (float*)p;
    cudaGetSymbolAddress(&p, g_Ah);    __half* Ah   = (__half*)p;
    cudaGetSymbolAddress(&p, g_Bhi);   __half* Bhi  = (__half*)p;
    cudaGetSymbolAddress(&p, g_Blo);   __half* Blo  = (__half*)p;

    // Wl fp16 split (independent of LSTM chain)
    cvt_bh<<<(Vocab * Hdim + 255) / 256, 256>>>(Wl, Bhi, Blo, Vocab * Hdim);

    // Layer 0 input projection
    gemm_nt_bias<<<dim3(Gdim / 64, Mrows / 64), 256>>>(
        x, W_ih0, b_ih0, b_hh0, xproj, Mrows, Gdim, INSZ);
    // Layer 0 recurrence -> h1 (fp32)
    lstm_layer<<<Bsz, Gdim>>>(xproj, W_hh0, h1, nullptr);
    // Layer 1 input projection
    gemm_nt_bias<<<dim3(Gdim / 64, Mrows / 64), 256>>>(
        h1, W_ih1, b_ih1, b_hh1, xproj, Mrows, Gdim, Hdim);
    // Layer 1 recurrence -> fp16 A directly
    lstm_layer<<<Bsz, Gdim>>>(xproj, W_hh1, nullptr, Ah);

    // Logits via pipelined HMMA fp16 2-pass
    cudaFuncSetAttribute(logits_gemm, cudaFuncAttributeMaxDynamicSharedMemorySize, LG_SMEM);
    logits_gemm<<<dim3(Vocab / 64, Mrows / (NM_TILES * 128)), 256, LG_SMEM>>>(
        Ah, Bhi, Blo, bl, out);
}

// round 7
// speedup vs baseline: 1.5313x; 1.0522x over previous
#include <cuda_runtime.h>
#include <cuda_fp16.h>
#include <cstdint>

// Problem constants
#define Bsz   64
#define Tlen  256
#define INSZ  256
#define Hdim  64
#define Gdim  256        // 4*Hdim
#define Vocab 8000
#define Mrows (Bsz * Tlen)   // 16384

// Scratch (device globals; no allocation allowed in kernel_launch)
__device__ float g_xproj[Mrows * Gdim];
__device__ float g_h1[Mrows * Hdim];
__device__ __align__(128) __half g_Ah[Mrows * Hdim];    // A rounded to fp16
__device__ __align__(128) __half g_Bh[Vocab * Hdim];    // 8*Wl rounded to fp16

// ---------------- packed f32x2 helpers ----------------
__device__ __forceinline__ unsigned long long pack2(float x) {
    unsigned long long r;
    asm("mov.b64 %0, {%1, %1};" : "=l"(r) : "f"(x));
    return r;
}
__device__ __forceinline__ unsigned long long pack2v(float x, float y) {
    unsigned long long r;
    asm("mov.b64 %0, {%1, %2};" : "=l"(r) : "f"(x), "f"(y));
    return r;
}
__device__ __forceinline__ void fma2(unsigned long long& d, unsigned long long a,
                                     unsigned long long b) {
    asm("fma.rn.f32x2 %0, %1, %2, %0;" : "+l"(d) : "l"(a), "l"(b));
}
__device__ __forceinline__ float2 unpack2(unsigned long long v) {
    float2 f;
    asm("mov.b64 {%0, %1}, %2;" : "=f"(f.x), "=f"(f.y) : "l"(v));
    return f;
}
__device__ __forceinline__ float fast_rcp(float x) {
    float r;
    asm("rcp.approx.f32 %0, %1;" : "=f"(r) : "f"(x));
    return r;
}
__device__ __forceinline__ float sigmoidf_(float x) {
    return fast_rcp(1.0f + __expf(-x));
}
__device__ __forceinline__ float tanh_fast(float x) {
    return 1.0f - 2.0f * fast_rcp(1.0f + __expf(2.0f * x));
}

// ---------------- generic C[M,N] = A[M,K] * B[N,K]^T + bias1 (+bias2) ----------------
__global__ void gemm_nt_bias(const float* __restrict__ A, const float* __restrict__ Bm,
                             const float* __restrict__ bias1, const float* __restrict__ bias2,
                             float* __restrict__ C, int M, int N, int K)
{
    __shared__ __align__(16) float As[64][17];
    __shared__ __align__(16) float Bs[16][68];

    const int t  = threadIdx.x;
    const int bm = blockIdx.y * 64;
    const int bn = blockIdx.x * 64;
    const int tm = (t >> 4) << 2;
    const int tn = (t & 15) << 2;
    const int lr = t >> 2;
    const int lk = (t & 3) << 2;

    unsigned long long acc[4][2];
#pragma unroll
    for (int i = 0; i < 4; i++) { acc[i][0] = 0ULL; acc[i][1] = 0ULL; }

    const float* Aptr = A  + (size_t)(bm + lr) * K + lk;
    const float* Bptr = Bm + (size_t)(bn + lr) * K + lk;

    for (int k0 = 0; k0 < K; k0 += 16) {
        float4 av = *reinterpret_cast<const float4*>(Aptr + k0);
        float4 bv = *reinterpret_cast<const float4*>(Bptr + k0);
        As[lr][lk + 0] = av.x; As[lr][lk + 1] = av.y;
        As[lr][lk + 2] = av.z; As[lr][lk + 3] = av.w;
        Bs[lk + 0][lr] = bv.x; Bs[lk + 1][lr] = bv.y;
        Bs[lk + 2][lr] = bv.z; Bs[lk + 3][lr] = bv.w;
        __syncthreads();
#pragma unroll
        for (int kk = 0; kk < 16; kk++) {
            unsigned long long b0 =
                *reinterpret_cast<const unsigned long long*>(&Bs[kk][tn]);
            unsigned long long b1 =
                *reinterpret_cast<const unsigned long long*>(&Bs[kk][tn + 2]);
#pragma unroll
            for (int i = 0; i < 4; i++) {
                unsigned long long ap = pack2(As[tm + i][kk]);
                fma2(acc[i][0], ap, b0);
                fma2(acc[i][1], ap, b1);
            }
        }
        __syncthreads();
    }

    float4 bvec;
    bvec.x = bias1[bn + tn + 0];
    bvec.y = bias1[bn + tn + 1];
    bvec.z = bias1[bn + tn + 2];
    bvec.w = bias1[bn + tn + 3];
    if (bias2) {
        bvec.x += bias2[bn + tn + 0];
        bvec.y += bias2[bn + tn + 1];
        bvec.z += bias2[bn + tn + 2];
        bvec.w += bias2[bn + tn + 3];
    }
#pragma unroll
    for (int i = 0; i < 4; i++) {
        float2 lo = unpack2(acc[i][0]);
        float2 hi = unpack2(acc[i][1]);
        float4 v = make_float4(lo.x + bvec.x, lo.y + bvec.y,
                               hi.x + bvec.z, hi.y + bvec.w);
        *reinterpret_cast<float4*>(&C[(size_t)(bm + tm + i) * N + bn + tn]) = v;
    }
}

// ---------------- LSTM recurrence (identical math to passing R6 version) ---------
__global__ void lstm_layer(const float* __restrict__ xproj,
                           const float* __restrict__ Whh,
                           float* __restrict__ hout,
                           __half* __restrict__ ah_out)
{
    __shared__ __align__(16) float h_sh[Hdim];
    __shared__ float gate_sh[Gdim];

    const int b = blockIdx.x;
    const int g = threadIdx.x;
    const int blk = g >> 6;

    unsigned long long wp[Hdim / 2];
#pragma unroll
    for (int j = 0; j < Hdim / 2; j++) {
        float2 v = *reinterpret_cast<const float2*>(Whh + g * Hdim + 2 * j);
        wp[j] = pack2v(v.x, v.y);
    }

    float c = 0.0f;
    if (g < Hdim) h_sh[g] = 0.0f;
    __syncthreads();

    const float* xp = xproj + (size_t)b * Tlen * Gdim;
    float xcur = xp[g];

    const unsigned long long* hp =
        reinterpret_cast<const unsigned long long*>(h_sh);

    for (int t = 0; t < Tlen; t++) {
        unsigned long long a0 = 0ULL, a1 = 0ULL, a2 = 0ULL, a3 = 0ULL;
        float xnext = (t + 1 < Tlen) ? xp[(size_t)(t + 1) * Gdim + g] : 0.0f;
#pragma unroll
        for (int j = 0; j < Hdim / 2; j += 4) {
            fma2(a0, wp[j + 0], hp[j + 0]);
            fma2(a1, wp[j + 1], hp[j + 1]);
            fma2(a2, wp[j + 2], hp[j + 2]);
            fma2(a3, wp[j + 3], hp[j + 3]);
        }
        float2 s0 = unpack2(a0), s1 = unpack2(a1), s2 = unpack2(a2), s3 = unpack2(a3);
        float val = xcur + (((s0.x + s0.y) + (s1.x + s1.y)) +
                            ((s2.x + s2.y) + (s3.x + s3.y)));
        xcur = xnext;

        float act = (blk == 2) ? tanh_fast(val) : sigmoidf_(val);
        gate_sh[g] = act;
        __syncthreads();

        if (g < Hdim) {
            float iv = gate_sh[g];
            float fv = gate_sh[g + Hdim];
            float gv = gate_sh[g + 2 * Hdim];
            float ov = gate_sh[g + 3 * Hdim];
            c = fv * c + iv * gv;
            float hn = ov * tanh_fast(c);
            h_sh[g] = hn;
            size_t idx = ((size_t)b * Tlen + t) * Hdim + g;
            if (hout) hout[idx] = hn;
            if (ah_out) ah_out[idx] = __float2half(hn);
        }
        __syncthreads();
    }
}

// ---------------- Wl -> fp16 (scaled by 8 for fp16 normal range) -------
__global__ void cvt_bh(const float* __restrict__ in, __half* __restrict__ out, int n)
{
    int i = blockIdx.x * blockDim.x + threadIdx.x;
    if (i < n) out[i] = __float2half(in[i] * 8.0f);
}

// ============ HMMA fp16 logits GEMM, streaming/pipelined, 1-pass ====================
// C = A_f16 * (8*Wl)_f16^T / 8 + bias.
// CTA: one bn (64 vocab cols, B resident 8KB) x 8 m-tiles of 128 rows,
// A double-buffered (2 x 16KB) via cp.async.
#define SWZ128(off) ((off) ^ (((off) >> 3) & 0x70))
#define LS_B    0
#define LS_A    8192
#define LS_ASTG 16384
#define LG_SMEM (8192 + 2 * 16384 + 1024)
#define NM_TILES 8

static __device__ __forceinline__ uint32_t smem_u32(const void* p) {
    uint32_t a;
    asm("{ .reg .u64 t; cvta.to.shared.u64 t, %1; cvt.u32.u64 %0, t; }"
        : "=r"(a) : "l"(p));
    return a;
}
__device__ __forceinline__ void cp16(uint32_t dst, const void* src) {
    asm volatile("cp.async.cg.shared.global [%0], [%1], 16;"
                 :: "r"(dst), "l"(src));
}
__device__ __forceinline__ void cp_commit() {
    asm volatile("cp.async.commit_group;" ::: "memory");
}
template <int N>
__device__ __forceinline__ void cp_wait() {
    asm volatile("cp.async.wait_group %0;" :: "n"(N) : "memory");
}
__device__ __forceinline__ void ldsm_x4(uint32_t& r0, uint32_t& r1, uint32_t& r2,
                                        uint32_t& r3, uint32_t addr) {
    asm volatile("ldmatrix.sync.aligned.m8n8.x4.shared.b16 {%0,%1,%2,%3}, [%4];"
                 : "=r"(r0), "=r"(r1), "=r"(r2), "=r"(r3) : "r"(addr));
}
__device__ __forceinline__ void mma_f16(float* c, uint32_t a0, uint32_t a1,
                                        uint32_t a2, uint32_t a3,
                                        uint32_t b0, uint32_t b1) {
    asm volatile("mma.sync.aligned.m16n8k16.row.col.f32.f16.f16.f32 "
                 "{%0,%1,%2,%3}, {%4,%5,%6,%7}, {%8,%9}, {%0,%1,%2,%3};"
                 : "+f"(c[0]), "+f"(c[1]), "+f"(c[2]), "+f"(c[3])
                 : "r"(a0), "r"(a1), "r"(a2), "r"(a3), "r"(b0), "r"(b1));
}
__device__ __forceinline__ void stg_cs_f2(float* p, float x, float y) {
    asm volatile("st.global.cs.v2.f32 [%0], {%1,%2};" :: "l"(p), "f"(x), "f"(y));
}

__device__ __forceinline__ void load_A_stage(uint32_t sA, const __half* Ah,
                                             int bm, int tid) {
    const int row = tid >> 1;            // 0..127
    const int cb = (tid & 1) * 4;        // chunk base 0 or 4
    const char* src = reinterpret_cast<const char*>(Ah + (size_t)(bm + row) * Hdim);
#pragma unroll
    for (int i = 0; i < 4; i++) {
        uint32_t off = SWZ128((uint32_t)(row * 128 + (cb + i) * 16));
        cp16(sA + off, src + (cb + i) * 16);
    }
}

__global__ void __launch_bounds__(256)
logits_gemm(const __half* __restrict__ Ah, const __half* __restrict__ Bh,
            const float* __restrict__ bias, float* __restrict__ C)
{
    extern __shared__ char smem_raw[];
    const uint32_t sb0 = smem_u32(smem_raw);
    const uint32_t sb = (sb0 + 1023) & ~1023u;

    const int tid = threadIdx.x;
    const int lane = tid & 31;
    const int wid = tid >> 5;
    const int wm = wid & 3;        // warp m-tile (0..3)
    const int wn = wid >> 2;       // warp n-tile (0..1)
    const int bn = blockIdx.x * 64;
    const int bm0 = blockIdx.y * (NM_TILES * 128);

    // ---- resident B tile (64 rows x 128B), cp.async ----
    {
        const int row = tid >> 2;            // 0..63
        const int cb = (tid & 3) * 2;        // chunks 0,2,4,6
        const char* src = reinterpret_cast<const char*>(Bh + (size_t)(bn + row) * Hdim);
#pragma unroll
        for (int i = 0; i < 2; i++) {
            uint32_t off = SWZ128((uint32_t)(row * 128 + (cb + i) * 16));
            cp16(sb + LS_B + off, src + (cb + i) * 16);
        }
    }
    load_A_stage(sb + LS_A, Ah, bm0, tid);
    cp_commit();

    const int gid = lane >> 2;
    const int tig = lane & 3;
    float2 bv[4];
#pragma unroll
    for (int nt = 0; nt < 4; nt++)
        bv[nt] = *reinterpret_cast<const float2*>(bias + bn + wn * 32 + nt * 8 + 2 * tig);

    const int rsel = lane & 15;
    const int csel = lane >> 4;

    for (int it = 0; it < NM_TILES; it++) {
        const uint32_t sA = sb + LS_A + (it & 1) * LS_ASTG;
        if (it + 1 < NM_TILES) {
            load_A_stage(sb + LS_A + ((it + 1) & 1) * LS_ASTG, Ah,
                         bm0 + (it + 1) * 128, tid);
            cp_commit();
            cp_wait<1>();
        } else {
            cp_wait<0>();
        }
        __syncthreads();

        float acc[2][4][4];
#pragma unroll
        for (int i = 0; i < 2; i++)
#pragma unroll
            for (int j = 0; j < 4; j++)
#pragma unroll
                for (int q = 0; q < 4; q++) acc[i][j][q] = 0.0f;

#pragma unroll
        for (int ks = 0; ks < 4; ks++) {
            const int col16 = ks * 2 + csel;
            uint32_t a[2][4];
#pragma unroll
            for (int mt = 0; mt < 2; mt++) {
                int row = wm * 32 + mt * 16 + rsel;
                uint32_t addr = sA + SWZ128((uint32_t)(row * 128 + col16 * 16));
                ldsm_x4(a[mt][0], a[mt][1], a[mt][2], a[mt][3], addr);
            }
            uint32_t b0[4], b1[4];
#pragma unroll
            for (int np = 0; np < 2; np++) {
                int row = wn * 32 + np * 16 + rsel;
                uint32_t addr = sb + LS_B + SWZ128((uint32_t)(row * 128 + col16 * 16));
                uint32_t r0, r1, r2, r3;
                ldsm_x4(r0, r1, r2, r3, addr);
                b0[np * 2 + 0] = r0; b0[np * 2 + 1] = r1;
                b1[np * 2 + 0] = r2; b1[np * 2 + 1] = r3;
            }
#pragma unroll
            for (int mt = 0; mt < 2; mt++)
#pragma unroll
                for (int nt = 0; nt < 4; nt++)
                    mma_f16(acc[mt][nt], a[mt][0], a[mt][1], a[mt][2], a[mt][3],
                            b0[nt], b1[nt]);
        }

        // epilogue: C = acc/8 + bias, streaming stores
        const int bm = bm0 + it * 128;
#pragma unroll
        for (int nt = 0; nt < 4; nt++) {
            const int gn = bn + wn * 32 + nt * 8 + 2 * tig;
#pragma unroll
            for (int mt = 0; mt < 2; mt++) {
                const int gm0 = bm + wm * 32 + mt * 16 + gid;
                float x0 = fmaf(acc[mt][nt][0], 0.125f, bv[nt].x);
                float y0 = fmaf(acc[mt][nt][1], 0.125f, bv[nt].y);
                float x1 = fmaf(acc[mt][nt][2], 0.125f, bv[nt].x);
                float y1 = fmaf(acc[mt][nt][3], 0.125f, bv[nt].y);
                stg_cs_f2(C + (size_t)gm0 * Vocab + gn, x0, y0);
                stg_cs_f2(C + (size_t)(gm0 + 8) * Vocab + gn, x1, y1);
            }
        }
        __syncthreads();
    }
}

// ------------------------------------ launch --------------------------------------
extern "C" void kernel_launch(void* const* d_in, const int* in_sizes, int n_in,
                              void* d_out, int out_size)
{
    (void)in_sizes; (void)n_in; (void)out_size;
    const float* x     = (const float*)d_in[0];
    const float* W_ih0 = (const float*)d_in[1];
    const float* W_hh0 = (const float*)d_in[2];
    const float* b_ih0 = (const float*)d_in[3];
    const float* b_hh0 = (const float*)d_in[4];
    const float* W_ih1 = (const float*)d_in[5];
    const float* W_hh1 = (const float*)d_in[6];
    const float* b_ih1 = (const float*)d_in[7];
    const float* b_hh1 = (const float*)d_in[8];
    const float* Wl    = (const float*)d_in[9];
    const float* bl    = (const float*)d_in[10];
    float* out = (float*)d_out;

    void* p;
    cudaGetSymbolAddress(&p, g_xproj); float* xproj = (float*)p;
    cudaGetSymbolAddress(&p, g_h1);    float* h1    = (float*)p;
    cudaGetSymbolAddress(&p, g_Ah);    __half* Ah   = (__half*)p;
    cudaGetSymbolAddress(&p, g_Bh);    __half* Bh   = (__half*)p;

    // Wl -> fp16 (independent of LSTM chain)
    cvt_bh<<<(Vocab * Hdim + 255) / 256, 256>>>(Wl, Bh, Vocab * Hdim);

    // Layer 0 input projection
    gemm_nt_bias<<<dim3(Gdim / 64, Mrows / 64), 256>>>(
        x, W_ih0, b_ih0, b_hh0, xproj, Mrows, Gdim, INSZ);
    // Layer 0 recurrence -> h1 (fp32)
    lstm_layer<<<Bsz, Gdim>>>(xproj, W_hh0, h1, nullptr);
    // Layer 1 input projection
    gemm_nt_bias<<<dim3(Gdim / 64, Mrows / 64), 256>>>(
        h1, W_ih1, b_ih1, b_hh1, xproj, Mrows, Gdim, Hdim);
    // Layer 1 recurrence -> fp16 A directly
    lstm_layer<<<Bsz, Gdim>>>(xproj, W_hh1, nullptr, Ah);

    // Logits via pipelined HMMA fp16 single pass
    cudaFuncSetAttribute(logits_gemm, cudaFuncAttributeMaxDynamicSharedMemorySize, LG_SMEM);
    logits_gemm<<<dim3(Vocab / 64, Mrows / (NM_TILES * 128)), 256, LG_SMEM>>>(
        Ah, Bh, bl, out);
}